// round 2
// baseline (speedup 1.0000x reference)
#include <cuda_runtime.h>

#define NB      32
#define NIN     1034
#define NOUT    512
#define STRIDE  1088          // NIN padded (need reads up to k0+32 and k+1)
#define KNS     1000.0f
#define MINW    (-0.3678794411714423f)
#define EF      2.718281828459045f

// scratch: sorted times, exp(t), t*exp(t), original index  (per batch row)
__device__ float g_ts [NB * STRIDE];
__device__ float g_z  [NB * STRIDE];
__device__ float g_zt [NB * STRIDE];
__device__ int   g_ord[NB * STRIDE];

// ---------------------------------------------------------------------------
// Kernel 1: per-batch bitonic sort of (time, idx) + precompute z, z*t
// ---------------------------------------------------------------------------
__global__ void sort_kernel(const float* __restrict__ x,
                            const float* __restrict__ pulse) {
    __shared__ unsigned long long s[2048];
    const int b   = blockIdx.x;
    const int tid = threadIdx.x;            // 1024 threads

    for (int i = tid; i < 2048; i += 1024) {
        float t;
        if (i < 1024)      t = x[b * 1024 + i];
        else if (i < NIN)  t = pulse[i - 1024];
        else               t = 3.0e38f;     // pad key (sorts to the end)
        // times are >= 0 so raw float bits are order-preserving as uint
        unsigned ub = __float_as_uint(t);
        s[i] = ((unsigned long long)ub << 32) | (unsigned)i;
    }
    __syncthreads();

    for (int k = 2; k <= 2048; k <<= 1) {
        for (int j = k >> 1; j > 0; j >>= 1) {
            for (int i = tid; i < 2048; i += 1024) {
                int ixj = i ^ j;
                if (ixj > i) {
                    unsigned long long a = s[i], c = s[ixj];
                    bool up = ((i & k) == 0);
                    if ((a > c) == up) { s[i] = c; s[ixj] = a; }
                }
            }
            __syncthreads();
        }
    }

    for (int i = tid; i < STRIDE; i += 1024) {
        int gi = b * STRIDE + i;
        if (i < NIN) {
            unsigned long long v = s[i];
            float t = __uint_as_float((unsigned)(v >> 32));
            int idx = (int)(unsigned)v;
            float z = expf(t);
            g_ts [gi] = t;
            g_z  [gi] = z;
            g_zt [gi] = z * t;
            g_ord[gi] = idx;
        } else {
            g_ts [gi] = KNS;   // sentinel: next_t for last element, invalid lanes
            g_z  [gi] = 0.0f;
            g_zt [gi] = 0.0f;
            g_ord[gi] = 0;
        }
    }
}

// ---------------------------------------------------------------------------
// Kernel 2: one warp per (batch, out-neuron). Chunked causal-set scan with
// warp-scan cumsum, Lambert-W threshold solve, first-valid early exit.
// ---------------------------------------------------------------------------
__global__ void solve_kernel(const float* __restrict__ W,
                             float* __restrict__ out) {
    const int gw   = (int)((blockIdx.x * blockDim.x + threadIdx.x) >> 5);
    const int lane = threadIdx.x & 31;
    const int b    = gw >> 9;        // /512
    const int o    = gw & 511;
    if (b >= NB) return;

    const float* __restrict__ ts  = g_ts  + b * STRIDE;
    const float* __restrict__ zz  = g_z   + b * STRIDE;
    const float* __restrict__ zts = g_zt  + b * STRIDE;
    const int*   __restrict__ ord = g_ord + b * STRIDE;
    const float* __restrict__ wrow = W + o * NIN;

    float carryA = 0.0f, carryB = 0.0f;
    float result = KNS;
    bool  done = false;

    for (int k0 = 0; k0 < NIN && !done; k0 += 32) {
        const int k = k0 + lane;
        const float t   = ts[k];
        const float z   = zz[k];
        const float zt_ = zts[k];
        const float w   = wrow[ord[k]];   // pad lanes: z=0 -> contribution 0

        float a  = w * z;
        float bb = w * zt_;
        // inclusive warp scan (Hillis-Steele)
        #pragma unroll
        for (int off = 1; off < 32; off <<= 1) {
            float ua = __shfl_up_sync(0xffffffffu, a,  off);
            float ub = __shfl_up_sync(0xffffffffu, bb, off);
            if (lane >= off) { a += ua; bb += ub; }
        }
        const float A = carryA + a;
        const float B = carryB + bb;
        const float totA = __shfl_sync(0xffffffffu, a,  31);
        const float totB = __shfl_sync(0xffffffffu, bb, 31);

        const bool  Apos  = A > 1e-10f;
        const float Asafe = Apos ? A : 1.0f;
        const float boa   = B / Asafe;
        const float arg   = (-1.0f / Asafe) * expf(fminf(boa, 80.0f));
        const bool  lam_ok = Apos && (arg >= MINW);

        // skip the Halley loop warp-uniformly while threshold unreachable
        if (__ballot_sync(0xffffffffu, lam_ok)) {
            float tc = 0.0f;
            bool valid = false;
            if (lam_ok) {
                // exact replica of the reference lambertw0 (f32, 12 Halley steps)
                float xw = fminf(fmaxf(arg, MINW), 0.0f);
                float wv = (xw < -0.25f)
                         ? (-1.0f + sqrtf(fmaxf(2.0f * (1.0f + EF * xw), 0.0f)))
                         : xw * (1.0f - xw);
                #pragma unroll
                for (int it = 0; it < 12; ++it) {
                    float ew = expf(wv);
                    float f  = wv * ew - xw;
                    float denom = ew * (wv + 1.0f)
                                - (wv + 2.0f) * f / (2.0f * (wv + 1.0f) + 1e-12f);
                    wv = wv - f / (denom + 1e-12f);
                }
                tc = boa - wv;
                const float nxt = ts[k + 1];       // k=NIN-1 reads sentinel KNS
                valid = (t < KNS) && (tc >= t) && (tc <= nxt);
            }
            const unsigned vm = __ballot_sync(0xffffffffu, valid);
            if (vm) {
                const int src = __ffs((int)vm) - 1;   // first (lowest-k) valid lane
                result = __shfl_sync(0xffffffffu, tc, src);
                done = true;
            }
        }
        carryA += totA;
        carryB += totB;
    }

    if (lane == 0) out[b * NOUT + o] = result;
}

// ---------------------------------------------------------------------------
extern "C" void kernel_launch(void* const* d_in, const int* in_sizes, int n_in,
                              void* d_out, int out_size) {
    const float* x      = (const float*)d_in[0];   // [32, 1024]
    const float* weight = (const float*)d_in[1];   // [512, 1034]
    const float* pulse  = (const float*)d_in[2];   // [10]
    float* out = (float*)d_out;                    // [32, 512]

    sort_kernel<<<NB, 1024>>>(x, pulse);

    // one warp per (b, o): 32*512 warps, 8 warps / block
    const int warps = NB * NOUT;
    solve_kernel<<<warps / 8, 256>>>(weight, out);
}

// round 3
// speedup vs baseline: 1.2045x; 1.2045x over previous
#include <cuda_runtime.h>

#define NB      32
#define NIN     1034
#define NOUT    512
#define STRIDE  1088
#define KNS     1000.0f
#define MINW    (-0.3678794411714423f)
#define EF      2.718281828459045f
#define NSLICE  8
#define SLEN    130        // ceil(1034/8)

// packed per-batch sorted data: (t, e^t, t*e^t, idx-as-float-bits)
__device__ float4 g_pack[NB * STRIDE];
// partial rank counts: [slice][b][i]
__device__ int    g_cntp[NSLICE * NB * NIN];

__device__ __forceinline__ float get_t(const float* __restrict__ x,
                                       const float* __restrict__ pulse,
                                       int b, int i) {
    return (i < 1024) ? x[b * 1024 + i] : pulse[i - 1024];
}

// ---------------------------------------------------------------------------
// Kernel 1: counting rank, partial over j-slices (no atomics, no sort)
// ---------------------------------------------------------------------------
__global__ void count_kernel(const float* __restrict__ x,
                             const float* __restrict__ pulse) {
    __shared__ float sj[SLEN];
    const int s = blockIdx.x;        // slice
    const int b = blockIdx.y;        // batch row
    const int j0 = s * SLEN;
    const int jn = min(SLEN, NIN - j0);

    for (int j = threadIdx.x; j < jn; j += blockDim.x)
        sj[j] = get_t(x, pulse, b, j0 + j);
    __syncthreads();

    for (int i = threadIdx.x; i < NIN; i += blockDim.x) {
        const float ti = get_t(x, pulse, b, i);
        int c = 0;
        #pragma unroll 4
        for (int j = 0; j < jn; ++j) {
            const float tj = sj[j];
            c += (tj < ti) || (tj == ti && (j0 + j) < i);   // stable rank
        }
        g_cntp[(s * NB + b) * NIN + i] = c;
    }
}

// ---------------------------------------------------------------------------
// Kernel 2: sum partial counts -> rank, scatter packed (t, z, z*t, idx)
// ---------------------------------------------------------------------------
__global__ void scatter_kernel(const float* __restrict__ x,
                               const float* __restrict__ pulse) {
    const int b = blockIdx.x;
    for (int i = threadIdx.x; i < STRIDE; i += blockDim.x) {
        if (i < NIN) {
            const float t = get_t(x, pulse, b, i);
            int r = 0;
            #pragma unroll
            for (int s = 0; s < NSLICE; ++s)
                r += g_cntp[(s * NB + b) * NIN + i];
            const float z = expf(t);
            g_pack[b * STRIDE + r] = make_float4(t, z, z * t, __int_as_float(i));
        } else {
            g_pack[b * STRIDE + i] = make_float4(KNS, 0.0f, 0.0f, 0.0f);
        }
    }
}

// ---------------------------------------------------------------------------
// Kernel 3: one warp per (batch, out-neuron). Chunked causal-set scan with
// log-prefilter, cheap Halley, first-valid early exit.
// ---------------------------------------------------------------------------
__global__ void solve_kernel(const float* __restrict__ W,
                             float* __restrict__ out) {
    const int gw   = (int)((blockIdx.x * blockDim.x + threadIdx.x) >> 5);
    const int lane = threadIdx.x & 31;
    const int b    = gw >> 9;
    const int o    = gw & 511;
    if (b >= NB) return;

    const float4* __restrict__ pk   = g_pack + b * STRIDE;
    const float*  __restrict__ wrow = W + o * NIN;

    float carryA = 0.0f, carryB = 0.0f;
    float result = KNS;
    bool  done = false;

    for (int k0 = 0; k0 < NIN && !done; k0 += 32) {
        const int k = k0 + lane;
        const float4 p = pk[k];
        const float t   = p.x;
        const float z   = p.y;
        const float zt_ = p.z;
        const float w   = wrow[__float_as_int(p.w)];

        float a  = w * z;
        float bb = w * zt_;
        #pragma unroll
        for (int off = 1; off < 32; off <<= 1) {
            const float ua = __shfl_up_sync(0xffffffffu, a,  off);
            const float ub = __shfl_up_sync(0xffffffffu, bb, off);
            if (lane >= off) { a += ua; bb += ub; }
        }
        const float A = carryA + a;
        const float B = carryB + bb;
        const float totA = __shfl_sync(0xffffffffu, a,  31);
        const float totB = __shfl_sync(0xffffffffu, bb, 31);

        const bool  Apos  = A > 1e-10f;
        const float Asafe = Apos ? A : 1.0f;
        const float boa   = __fdividef(B, Asafe);

        // next input spike time (window upper bound) — convergent shfl
        float nxt = __shfl_down_sync(0xffffffffu, t, 1);
        if (lane == 31) nxt = pk[k0 + 32].x;

        // cheap prefilter: arg >= -1/e  <=>  ln(A) >= B/A + 1  (boa < 80 here)
        const bool quick = Apos && (__logf(Asafe) >= boa + 0.98f);

        if (__ballot_sync(0xffffffffu, quick)) {
            float tc = 0.0f;
            bool valid = false;
            if (quick) {
                // accurate arg, exactly like the reference
                const float arg = -__fdividef(1.0f, Asafe) * expf(fminf(boa, 80.0f));
                if (arg >= MINW) {
                    float xw = fmaxf(fminf(arg, 0.0f), MINW);
                    float wv = (xw < -0.25f)
                             ? (-1.0f + sqrtf(fmaxf(2.0f * (1.0f + EF * xw), 0.0f)))
                             : xw * (1.0f - xw);
                    // 6 fast Halley steps (MUFU exp) ...
                    #pragma unroll
                    for (int it = 0; it < 6; ++it) {
                        const float ew = __expf(wv);
                        const float f  = wv * ew - xw;
                        const float denom = ew * (wv + 1.0f)
                                  - (wv + 2.0f) * f / (2.0f * (wv + 1.0f) + 1e-12f);
                        wv = wv - f / (denom + 1e-12f);
                    }
                    // ... then 2 accurate polish steps to land on the reference fixpoint
                    #pragma unroll
                    for (int it = 0; it < 2; ++it) {
                        const float ew = expf(wv);
                        const float f  = wv * ew - xw;
                        const float denom = ew * (wv + 1.0f)
                                  - (wv + 2.0f) * f / (2.0f * (wv + 1.0f) + 1e-12f);
                        wv = wv - f / (denom + 1e-12f);
                    }
                    tc = boa - wv;
                    valid = (t < KNS) && (tc >= t) && (tc <= nxt);
                }
            }
            const unsigned vm = __ballot_sync(0xffffffffu, valid);
            if (vm) {
                const int src = __ffs((int)vm) - 1;
                result = __shfl_sync(0xffffffffu, tc, src);
                done = true;
            }
        }
        carryA += totA;
        carryB += totB;
    }

    if (lane == 0) out[b * NOUT + o] = result;
}

// ---------------------------------------------------------------------------
extern "C" void kernel_launch(void* const* d_in, const int* in_sizes, int n_in,
                              void* d_out, int out_size) {
    const float* x      = (const float*)d_in[0];   // [32, 1024]
    const float* weight = (const float*)d_in[1];   // [512, 1034]
    const float* pulse  = (const float*)d_in[2];   // [10]
    float* out = (float*)d_out;                    // [32, 512]

    count_kernel<<<dim3(NSLICE, NB), 256>>>(x, pulse);
    scatter_kernel<<<NB, 256>>>(x, pulse);

    const int warps = NB * NOUT;
    solve_kernel<<<warps / 8, 256>>>(weight, out);
}

// round 4
// speedup vs baseline: 1.9115x; 1.5870x over previous
#include <cuda_runtime.h>

#define NB      32
#define NIN     1034
#define NOUT    512
#define STRIDE  1088
#define KNS     1000.0f
#define MINW    (-0.3678794411714423f)
#define EF      2.718281828459045f
#define NBUCK   2048

// packed per-batch sorted data: (t, e^t, t*e^t, idx-as-int-bits)
__device__ float4 g_pack[NB * STRIDE];

__device__ __forceinline__ float get_t(const float* __restrict__ x,
                                       const float* __restrict__ pulse,
                                       int b, int i) {
    return (i < 1024) ? x[b * 1024 + i] : pulse[i - 1024];
}

__device__ __forceinline__ int bucket_of(float t) {
    // t >= 0; floor(t*NBUCK) is monotone in t. Clamp for t >= 1.
    int bid = (int)(t * (float)NBUCK);
    return bid < 0 ? 0 : (bid >= NBUCK ? NBUCK - 1 : bid);
}

// ---------------------------------------------------------------------------
// Kernel 1: per-batch bucket sort + pack.  grid=NB, block=1024.
// ---------------------------------------------------------------------------
__global__ void sort_pack_kernel(const float* __restrict__ x,
                                 const float* __restrict__ pulse) {
    __shared__ int cnt [NBUCK];     // histogram, then consumed as fill ptrs
    __shared__ int base[NBUCK];     // stable bucket starts (kept for sort bounds)
    __shared__ unsigned long long keys[NIN];
    __shared__ float wsum[32];

    const int b   = blockIdx.x;
    const int tid = threadIdx.x;            // 1024 threads
    const int lane = tid & 31, wid = tid >> 5;

    // 1) clear histogram
    cnt[tid] = 0; cnt[tid + 1024] = 0;
    __syncthreads();

    // 2) histogram
    for (int i = tid; i < NIN; i += 1024) {
        const float t = get_t(x, pulse, b, i);
        atomicAdd(&cnt[bucket_of(t)], 1);
    }
    __syncthreads();

    // 3) exclusive prefix sum over 2048 buckets (2 per thread)
    {
        const int v0 = cnt[2 * tid], v1 = cnt[2 * tid + 1];
        float s = (float)(v0 + v1);          // counts small; float exact < 2^24
        #pragma unroll
        for (int off = 1; off < 32; off <<= 1) {
            const float u = __shfl_up_sync(0xffffffffu, s, off);
            if (lane >= off) s += u;
        }
        if (lane == 31) wsum[wid] = s;
        __syncthreads();
        if (wid == 0) {
            float ws = wsum[lane];
            #pragma unroll
            for (int off = 1; off < 32; off <<= 1) {
                const float u = __shfl_up_sync(0xffffffffu, ws, off);
                if (lane >= off) ws += u;
            }
            wsum[lane] = ws;
        }
        __syncthreads();
        const int incl = (int)s + (wid ? (int)wsum[wid - 1] : 0);
        const int excl = incl - v0 - v1;
        base[2 * tid]     = excl;
        base[2 * tid + 1] = excl + v0;
        __syncthreads();
        cnt[2 * tid]     = excl;             // fill pointers
        cnt[2 * tid + 1] = excl + v0;
    }
    __syncthreads();

    // 4) scatter stable u64 keys (t_bits<<32 | idx) into bucket slots
    for (int i = tid; i < NIN; i += 1024) {
        const float t = get_t(x, pulse, b, i);
        const int pos = atomicAdd(&cnt[bucket_of(t)], 1);
        keys[pos] = ((unsigned long long)__float_as_uint(t) << 32) | (unsigned)i;
    }
    __syncthreads();

    // 5) intra-bucket insertion sort (one thread per bucket; sizes tiny)
    for (int bk = tid; bk < NBUCK; bk += 1024) {
        const int s0 = base[bk];
        const int s1 = (bk + 1 < NBUCK) ? base[bk + 1] : NIN;
        for (int i = s0 + 1; i < s1; ++i) {
            const unsigned long long v = keys[i];
            int j = i - 1;
            while (j >= s0 && keys[j] > v) { keys[j + 1] = keys[j]; --j; }
            keys[j + 1] = v;
        }
    }
    __syncthreads();

    // 6) pack
    for (int i = tid; i < STRIDE; i += 1024) {
        if (i < NIN) {
            const unsigned long long v = keys[i];
            const float t = __uint_as_float((unsigned)(v >> 32));
            const int idx = (int)(unsigned)v;
            const float z = expf(t);
            g_pack[b * STRIDE + i] = make_float4(t, z, z * t, __int_as_float(idx));
        } else {
            g_pack[b * STRIDE + i] = make_float4(KNS, 0.0f, 0.0f, 0.0f);
        }
    }
}

// ---------------------------------------------------------------------------
// Kernel 2: one warp per (batch, out-neuron). Chunked causal-set scan with
// log-prefilter, fast Halley + single accurate polish, early exit.
// ---------------------------------------------------------------------------
__global__ void solve_kernel(const float* __restrict__ W,
                             float* __restrict__ out) {
    const int gw   = (int)((blockIdx.x * blockDim.x + threadIdx.x) >> 5);
    const int lane = threadIdx.x & 31;
    const int b    = gw >> 9;
    const int o    = gw & 511;
    if (b >= NB) return;

    const float4* __restrict__ pk   = g_pack + b * STRIDE;
    const float*  __restrict__ wrow = W + o * NIN;

    float carryA = 0.0f, carryB = 0.0f;
    float result = KNS;
    bool  done = false;

    for (int k0 = 0; k0 < NIN && !done; k0 += 32) {
        const int k = k0 + lane;
        const float4 p = pk[k];
        const float t   = p.x;
        const float z   = p.y;
        const float zt_ = p.z;
        const float w   = wrow[__float_as_int(p.w)];

        float a  = w * z;
        float bb = w * zt_;
        #pragma unroll
        for (int off = 1; off < 32; off <<= 1) {
            const float ua = __shfl_up_sync(0xffffffffu, a,  off);
            const float ub = __shfl_up_sync(0xffffffffu, bb, off);
            if (lane >= off) { a += ua; bb += ub; }
        }
        const float A = carryA + a;
        const float B = carryB + bb;
        const float totA = __shfl_sync(0xffffffffu, a,  31);
        const float totB = __shfl_sync(0xffffffffu, bb, 31);

        const bool  Apos  = A > 1e-10f;
        const float Asafe = Apos ? A : 1.0f;
        const float boa   = __fdividef(B, Asafe);

        float nxt = __shfl_down_sync(0xffffffffu, t, 1);
        if (lane == 31) nxt = pk[k0 + 32].x;

        // cheap prefilter: arg >= -1/e  <=>  ln(A) >= B/A + 1  (with margin)
        const bool quick = Apos && (__logf(Asafe) >= boa + 0.98f);

        if (__ballot_sync(0xffffffffu, quick)) {
            float tc = 0.0f;
            bool valid = false;
            if (quick) {
                const float arg = -__fdividef(1.0f, Asafe) * expf(fminf(boa, 80.0f));
                if (arg >= MINW) {
                    float xw = fmaxf(fminf(arg, 0.0f), MINW);
                    float wv = (xw < -0.25f)
                             ? (-1.0f + sqrtf(fmaxf(2.0f * (1.0f + EF * xw), 0.0f)))
                             : xw * (1.0f - xw);
                    #pragma unroll
                    for (int it = 0; it < 6; ++it) {
                        const float ew = __expf(wv);
                        const float f  = wv * ew - xw;
                        const float denom = ew * (wv + 1.0f)
                                  - (wv + 2.0f) * f / (2.0f * (wv + 1.0f) + 1e-12f);
                        wv = wv - f / (denom + 1e-12f);
                    }
                    {   // one accurate polish step to land on the reference fixpoint
                        const float ew = expf(wv);
                        const float f  = wv * ew - xw;
                        const float denom = ew * (wv + 1.0f)
                                  - (wv + 2.0f) * f / (2.0f * (wv + 1.0f) + 1e-12f);
                        wv = wv - f / (denom + 1e-12f);
                    }
                    tc = boa - wv;
                    valid = (t < KNS) && (tc >= t) && (tc <= nxt);
                }
            }
            const unsigned vm = __ballot_sync(0xffffffffu, valid);
            if (vm) {
                const int src = __ffs((int)vm) - 1;
                result = __shfl_sync(0xffffffffu, tc, src);
                done = true;
            }
        }
        carryA += totA;
        carryB += totB;
    }

    if (lane == 0) out[b * NOUT + o] = result;
}

// ---------------------------------------------------------------------------
extern "C" void kernel_launch(void* const* d_in, const int* in_sizes, int n_in,
                              void* d_out, int out_size) {
    const float* x      = (const float*)d_in[0];   // [32, 1024]
    const float* weight = (const float*)d_in[1];   // [512, 1034]
    const float* pulse  = (const float*)d_in[2];   // [10]
    float* out = (float*)d_out;                    // [32, 512]

    sort_pack_kernel<<<NB, 1024>>>(x, pulse);

    const int warps = NB * NOUT;
    solve_kernel<<<warps / 8, 256>>>(weight, out);
}

// round 5
// speedup vs baseline: 2.8731x; 1.5031x over previous
#include <cuda_runtime.h>

#define NB      32
#define NIN     1034
#define NOUT    512
#define STRIDE  1088
#define KNS     1000.0f
#define MINW    (-0.3678794411714423f)
#define EF      2.718281828459045f
#define NBUCK   2048

// packed per-batch sorted data: (t, e^t, t*e^t, idx-as-int-bits)
__device__ float4 g_pack[NB * STRIDE];

__device__ __forceinline__ float get_t(const float* __restrict__ x,
                                       const float* __restrict__ pulse,
                                       int b, int i) {
    return (i < 1024) ? x[b * 1024 + i] : pulse[i - 1024];
}

__device__ __forceinline__ int bucket_of(float t) {
    int bid = (int)(t * (float)NBUCK);
    return bid < 0 ? 0 : (bid >= NBUCK ? NBUCK - 1 : bid);
}

// ---------------------------------------------------------------------------
// Kernel 1: per-batch bucket sort + pack.  grid=NB, block=1024.
// ---------------------------------------------------------------------------
__global__ void sort_pack_kernel(const float* __restrict__ x,
                                 const float* __restrict__ pulse) {
    __shared__ int cnt [NBUCK];
    __shared__ int base[NBUCK];
    __shared__ unsigned long long keys[NIN];
    __shared__ float wsum[32];

    const int b   = blockIdx.x;
    const int tid = threadIdx.x;
    const int lane = tid & 31, wid = tid >> 5;

    cnt[tid] = 0; cnt[tid + 1024] = 0;
    __syncthreads();

    for (int i = tid; i < NIN; i += 1024) {
        const float t = get_t(x, pulse, b, i);
        atomicAdd(&cnt[bucket_of(t)], 1);
    }
    __syncthreads();

    {
        const int v0 = cnt[2 * tid], v1 = cnt[2 * tid + 1];
        float s = (float)(v0 + v1);
        #pragma unroll
        for (int off = 1; off < 32; off <<= 1) {
            const float u = __shfl_up_sync(0xffffffffu, s, off);
            if (lane >= off) s += u;
        }
        if (lane == 31) wsum[wid] = s;
        __syncthreads();
        if (wid == 0) {
            float ws = wsum[lane];
            #pragma unroll
            for (int off = 1; off < 32; off <<= 1) {
                const float u = __shfl_up_sync(0xffffffffu, ws, off);
                if (lane >= off) ws += u;
            }
            wsum[lane] = ws;
        }
        __syncthreads();
        const int incl = (int)s + (wid ? (int)wsum[wid - 1] : 0);
        const int excl = incl - v0 - v1;
        base[2 * tid]     = excl;
        base[2 * tid + 1] = excl + v0;
        __syncthreads();
        cnt[2 * tid]     = excl;
        cnt[2 * tid + 1] = excl + v0;
    }
    __syncthreads();

    for (int i = tid; i < NIN; i += 1024) {
        const float t = get_t(x, pulse, b, i);
        const int pos = atomicAdd(&cnt[bucket_of(t)], 1);
        keys[pos] = ((unsigned long long)__float_as_uint(t) << 32) | (unsigned)i;
    }
    __syncthreads();

    for (int bk = tid; bk < NBUCK; bk += 1024) {
        const int s0 = base[bk];
        const int s1 = (bk + 1 < NBUCK) ? base[bk + 1] : NIN;
        for (int i = s0 + 1; i < s1; ++i) {
            const unsigned long long v = keys[i];
            int j = i - 1;
            while (j >= s0 && keys[j] > v) { keys[j + 1] = keys[j]; --j; }
            keys[j + 1] = v;
        }
    }
    __syncthreads();

    for (int i = tid; i < STRIDE; i += 1024) {
        if (i < NIN) {
            const unsigned long long v = keys[i];
            const float t = __uint_as_float((unsigned)(v >> 32));
            const int idx = (int)(unsigned)v;
            const float z = expf(t);
            g_pack[b * STRIDE + i] = make_float4(t, z, z * t, __int_as_float(idx));
        } else {
            g_pack[b * STRIDE + i] = make_float4(KNS, 0.0f, 0.0f, 0.0f);
        }
    }
}

// packed f32x2 helpers (Blackwell)
__device__ __forceinline__ unsigned long long pack2(float lo, float hi) {
    unsigned long long r;
    asm("mov.b64 %0, {%1, %2};" : "=l"(r) : "f"(lo), "f"(hi));
    return r;
}
__device__ __forceinline__ void unpack2(unsigned long long v, float& lo, float& hi) {
    asm("mov.b64 {%0, %1}, %2;" : "=f"(lo), "=f"(hi) : "l"(v));
}
__device__ __forceinline__ unsigned long long addf32x2(unsigned long long a,
                                                       unsigned long long b) {
    unsigned long long r;
    asm("add.rn.f32x2 %0, %1, %2;" : "=l"(r) : "l"(a), "l"(b));
    return r;
}

// ---------------------------------------------------------------------------
// Kernel 2: one warp per (batch, out-neuron). Packed f32x2 warp scan,
// log-prefilter, 2-iteration Lambert W (good init + fast + accurate polish).
// ---------------------------------------------------------------------------
__global__ void solve_kernel(const float* __restrict__ W,
                             float* __restrict__ out) {
    const int gw   = (int)((blockIdx.x * blockDim.x + threadIdx.x) >> 5);
    const int lane = threadIdx.x & 31;
    const int b    = gw >> 9;
    const int o    = gw & 511;

    const float4* __restrict__ pk   = g_pack + b * STRIDE;
    const float*  __restrict__ wrow = W + o * NIN;

    unsigned long long carry = pack2(0.0f, 0.0f);
    float result = KNS;
    bool  done = false;

    for (int k0 = 0; k0 < NIN && !done; k0 += 32) {
        const int k = k0 + lane;
        const float4 p = pk[k];
        const float t = p.x;
        const float w = wrow[__float_as_int(p.w)];

        // packed (A, B) inclusive warp scan
        unsigned long long ab = pack2(w * p.y, w * p.z);
        #pragma unroll
        for (int off = 1; off < 32; off <<= 1) {
            const unsigned long long u = __shfl_up_sync(0xffffffffu, ab, off);
            if (lane >= off) ab = addf32x2(ab, u);
        }
        const unsigned long long tot = __shfl_sync(0xffffffffu, ab, 31);
        const unsigned long long cum = addf32x2(carry, ab);

        float A, B;
        unpack2(cum, A, B);

        const bool  Apos  = A > 1e-10f;
        const float Asafe = Apos ? A : 1.0f;
        const float boa   = __fdividef(B, Asafe);

        float nxt = __shfl_down_sync(0xffffffffu, t, 1);
        if (lane == 31) nxt = pk[k0 + 32].x;

        // cheap prefilter: arg >= -1/e  <=>  ln(A) >= B/A + 1  (0.02 margin)
        const bool quick = Apos && (__logf(Asafe) >= boa + 0.98f);

        if (__ballot_sync(0xffffffffu, quick)) {
            float tc = 0.0f;
            bool valid = false;
            if (quick) {
                // accurate arg (reference formula)
                const float arg = -__fdividef(1.0f, Asafe) * expf(fminf(boa, 80.0f));
                if (arg >= MINW) {
                    const float xw = fmaxf(fminf(arg, 0.0f), MINW);
                    float wv;
                    if (xw < -0.25f) {
                        // 3-term branch-point series: w = -1 + p - p^2/3 + 11p^3/72
                        const float pbr = sqrtf(fmaxf(2.0f * (1.0f + EF * xw), 0.0f));
                        wv = -1.0f + pbr * (1.0f + pbr * (-0.33333333f + pbr * 0.15277778f));
                    } else {
                        // 3-term Taylor: w = x - x^2 + 1.5 x^3
                        wv = xw * (1.0f - xw * (1.0f - 1.5f * xw));
                    }
                    {   // 1 fast Halley step (MUFU exp, fast div)
                        const float ew = __expf(wv);
                        const float f  = wv * ew - xw;
                        const float denom = ew * (wv + 1.0f)
                                  - __fdividef((wv + 2.0f) * f,
                                               2.0f * (wv + 1.0f) + 1e-12f);
                        wv = wv - __fdividef(f, denom + 1e-12f);
                    }
                    {   // 1 accurate polish step (lands on the reference fixpoint)
                        const float ew = expf(wv);
                        const float f  = wv * ew - xw;
                        const float denom = ew * (wv + 1.0f)
                                  - (wv + 2.0f) * f / (2.0f * (wv + 1.0f) + 1e-12f);
                        wv = wv - f / (denom + 1e-12f);
                    }
                    tc = boa - wv;
                    valid = (t < KNS) && (tc >= t) && (tc <= nxt);
                }
            }
            const unsigned vm = __ballot_sync(0xffffffffu, valid);
            if (vm) {
                const int src = __ffs((int)vm) - 1;
                result = __shfl_sync(0xffffffffu, tc, src);
                done = true;
            }
        }
        carry = addf32x2(carry, tot);
    }

    if (lane == 0) out[b * NOUT + o] = result;
}

// ---------------------------------------------------------------------------
extern "C" void kernel_launch(void* const* d_in, const int* in_sizes, int n_in,
                              void* d_out, int out_size) {
    const float* x      = (const float*)d_in[0];   // [32, 1024]
    const float* weight = (const float*)d_in[1];   // [512, 1034]
    const float* pulse  = (const float*)d_in[2];   // [10]
    float* out = (float*)d_out;                    // [32, 512]

    sort_pack_kernel<<<NB, 1024>>>(x, pulse);

    const int warps = NB * NOUT;
    solve_kernel<<<warps / 8, 256>>>(weight, out);
}